// round 1
// baseline (speedup 1.0000x reference)
#include <cuda_runtime.h>
#include <math.h>

#define Bb 8
#define SS 2048
#define DD 1024
#define HH 16
#define DHH 64
#define MM (Bb * SS)
#define SCALE 0.125f

// ---------------- scratch (device globals; no allocation allowed) ----------
__device__ float g_q[(size_t)MM * DD];    // 64 MB: mixed_query_layer
__device__ float g_k[(size_t)MM * DD];    // 64 MB: mixed_key_layer
__device__ float g_ql[(size_t)MM * HH];   // 1 MB : q attention logits
__device__ float g_pq[Bb * HH * DHH];     // pooled_q
__device__ float g_pk[Bb * HH * DHH];     // pooled_k, flat == pk[b][d]

// ---------------- big SGEMM: 128x128x16 tile, 8x8 microtile, 256 thr -------
// MODE 0: C = A @ W + bias
// MODE 1: C = (A * pk_row) @ W + bias + resid   (final transform + residual)
template <int MODE>
__global__ void __launch_bounds__(256, 2)
sgemm_kernel(const float* __restrict__ A, const float* __restrict__ W,
             const float* __restrict__ bias, float* __restrict__ C,
             const float* __restrict__ pk, const float* __restrict__ resid)
{
    constexpr int BM = 128, BN = 128, BK = 16;
    __shared__ float As[BK][BM + 4];
    __shared__ float Bs[BK][BN];

    const int n0 = blockIdx.x * BN;
    const int m0 = blockIdx.y * BM;
    const int tid = threadIdx.x;
    const int tx = tid & 15;
    const int ty = tid >> 4;
    const int batch = m0 / SS;   // 128 | 2048, so one batch per block-row

    float acc[8][8];
#pragma unroll
    for (int i = 0; i < 8; i++)
#pragma unroll
        for (int j = 0; j < 8; j++) acc[i][j] = 0.0f;

    for (int k0 = 0; k0 < DD; k0 += BK) {
        // --- load A tile (transposed into SMEM) ---
#pragma unroll
        for (int r = 0; r < 2; r++) {
            int idx  = tid * 2 + r;          // 0..511
            int arow = idx >> 2;             // 0..127
            int ac   = (idx & 3) << 2;       // 0,4,8,12
            float4 v = *(const float4*)(A + (size_t)(m0 + arow) * DD + k0 + ac);
            if (MODE == 1) {
                float4 p = *(const float4*)(pk + batch * DD + k0 + ac);
                v.x *= p.x; v.y *= p.y; v.z *= p.z; v.w *= p.w;
            }
            As[ac + 0][arow] = v.x;
            As[ac + 1][arow] = v.y;
            As[ac + 2][arow] = v.z;
            As[ac + 3][arow] = v.w;
        }
        // --- load B tile ---
#pragma unroll
        for (int r = 0; r < 2; r++) {
            int idx  = tid * 2 + r;
            int brow = idx >> 5;             // 0..15
            int bc   = (idx & 31) << 2;      // 0..124
            *(float4*)&Bs[brow][bc] =
                *(const float4*)(W + (size_t)(k0 + brow) * DD + n0 + bc);
        }
        __syncthreads();

#pragma unroll
        for (int kk = 0; kk < BK; kk++) {
            float af[8], bf[8];
            *(float4*)&af[0] = *(const float4*)&As[kk][ty * 8];
            *(float4*)&af[4] = *(const float4*)&As[kk][ty * 8 + 4];
            *(float4*)&bf[0] = *(const float4*)&Bs[kk][tx * 8];
            *(float4*)&bf[4] = *(const float4*)&Bs[kk][tx * 8 + 4];
#pragma unroll
            for (int i = 0; i < 8; i++)
#pragma unroll
                for (int j = 0; j < 8; j++) acc[i][j] += af[i] * bf[j];
        }
        __syncthreads();
    }

    // --- epilogue ---
#pragma unroll
    for (int i = 0; i < 8; i++) {
        int m = m0 + ty * 8 + i;
        float*       crow = C + (size_t)m * DD + n0 + tx * 8;
        const float* rrow = resid + (size_t)m * DD + n0 + tx * 8;
#pragma unroll
        for (int j = 0; j < 8; j++) {
            float v = acc[i][j] + bias[n0 + tx * 8 + j];
            if (MODE == 1) v += rrow[j];
            crow[j] = v;
        }
    }
}

// ---------------- q attention logits: ql[m][h] = q[m,:] @ Wqa[:,h] + bqa ---
__global__ void __launch_bounds__(256)
qlogits_kernel(const float* __restrict__ Wqa, const float* __restrict__ bqa,
               const float* __restrict__ q, float* __restrict__ ql)
{
    extern __shared__ float sW[];   // [HH][DD] transposed, 64 KB
    int tid = threadIdx.x;
    for (int i = tid; i < DD * HH; i += 256) {
        int k = i >> 4, h = i & 15;
        sW[h * DD + k] = Wqa[i];
    }
    __syncthreads();

    int warp = tid >> 5, lane = tid & 31;
    for (int rr = 0; rr < 8; rr++) {
        int m = blockIdx.x * 64 + warp * 8 + rr;
        const float* qrow = q + (size_t)m * DD;
        float acc[HH];
#pragma unroll
        for (int h = 0; h < HH; h++) acc[h] = 0.0f;
        for (int k = lane; k < DD; k += 32) {
            float qv = qrow[k];
#pragma unroll
            for (int h = 0; h < HH; h++) acc[h] += qv * sW[h * DD + k];
        }
#pragma unroll
        for (int h = 0; h < HH; h++)
#pragma unroll
            for (int off = 16; off; off >>= 1)
                acc[h] += __shfl_xor_sync(0xffffffffu, acc[h], off);
        if (lane == 0) {
#pragma unroll
            for (int h = 0; h < HH; h++)
                ql[(size_t)m * HH + h] = acc[h] + bqa[h];
        }
    }
}

// ---------------- softmax over S of q logits + pooled_q --------------------
__global__ void __launch_bounds__(256)
softmax_pool_q(const float* __restrict__ mask, const float* __restrict__ ql,
               const float* __restrict__ q, float* __restrict__ pq)
{
    __shared__ float w[SS];
    __shared__ float red[256];
    int b = blockIdx.x >> 4, h = blockIdx.x & 15;
    int tid = threadIdx.x;

    float lv[8];
    float lmax = -1e30f;
#pragma unroll
    for (int i = 0; i < 8; i++) {
        int s = tid + i * 256;
        float l = ql[((size_t)(b * SS + s)) * HH + h] * SCALE + mask[b * SS + s];
        lv[i] = l;
        lmax = fmaxf(lmax, l);
    }
    red[tid] = lmax; __syncthreads();
    for (int off = 128; off; off >>= 1) {
        if (tid < off) red[tid] = fmaxf(red[tid], red[tid + off]);
        __syncthreads();
    }
    float mx = red[0];
    __syncthreads();

    float lsum = 0.0f;
#pragma unroll
    for (int i = 0; i < 8; i++) {
        float e = __expf(lv[i] - mx);
        w[tid + i * 256] = e;
        lsum += e;
    }
    red[tid] = lsum; __syncthreads();
    for (int off = 128; off; off >>= 1) {
        if (tid < off) red[tid] += red[tid + off];
        __syncthreads();
    }
    float inv = 1.0f / red[0];
    __syncthreads();

    int g = tid >> 6, dh = tid & 63;
    const float* qb = q + (size_t)(b * SS) * DD + h * DHH + dh;
    float acc = 0.0f;
    for (int s = g; s < SS; s += 4) acc += w[s] * qb[(size_t)s * DD];
    red[tid] = acc; __syncthreads();
    if (tid < 64)
        pq[blockIdx.x * DHH + tid] =
            (red[tid] + red[tid + 64] + red[tid + 128] + red[tid + 192]) * inv;
}

// ---------------- qk scores (k . pooled_q), softmax, pooled_k --------------
__global__ void __launch_bounds__(256)
softmax_pool_k(const float* __restrict__ mask, const float* __restrict__ kx,
               const float* __restrict__ pq, float* __restrict__ pk)
{
    __shared__ float w[SS];
    __shared__ float red[256];
    __shared__ float spq[DHH];
    int b = blockIdx.x >> 4, h = blockIdx.x & 15;
    int tid = threadIdx.x;

    if (tid < DHH) spq[tid] = pq[blockIdx.x * DHH + tid];
    __syncthreads();

    int warp = tid >> 5, lane = tid & 31;
    float p0 = spq[lane], p1 = spq[lane + 32];
    const float* kb = kx + (size_t)(b * SS) * DD + h * DHH;
    for (int s = warp; s < SS; s += 8) {
        const float* kr = kb + (size_t)s * DD;
        float part = kr[lane] * p0 + kr[lane + 32] * p1;
#pragma unroll
        for (int off = 16; off; off >>= 1)
            part += __shfl_xor_sync(0xffffffffu, part, off);
        if (lane == 0) w[s] = part * SCALE + mask[b * SS + s];
    }
    __syncthreads();

    float lv[8];
    float lmax = -1e30f;
#pragma unroll
    for (int i = 0; i < 8; i++) {
        float l = w[tid + i * 256];
        lv[i] = l;
        lmax = fmaxf(lmax, l);
    }
    red[tid] = lmax; __syncthreads();
    for (int off = 128; off; off >>= 1) {
        if (tid < off) red[tid] = fmaxf(red[tid], red[tid + off]);
        __syncthreads();
    }
    float mx = red[0];
    __syncthreads();

    float lsum = 0.0f;
#pragma unroll
    for (int i = 0; i < 8; i++) {
        float e = __expf(lv[i] - mx);
        w[tid + i * 256] = e;
        lsum += e;
    }
    red[tid] = lsum; __syncthreads();
    for (int off = 128; off; off >>= 1) {
        if (tid < off) red[tid] += red[tid + off];
        __syncthreads();
    }
    float inv = 1.0f / red[0];
    __syncthreads();

    int g = tid >> 6, dh = tid & 63;
    const float* kb2 = kb + dh;
    float acc = 0.0f;
    for (int s = g; s < SS; s += 4) acc += w[s] * kb2[(size_t)s * DD];
    red[tid] = acc; __syncthreads();
    if (tid < 64)
        pk[blockIdx.x * DHH + tid] =
            (red[tid] + red[tid + 64] + red[tid + 128] + red[tid + 192]) * inv;
}

// ---------------------------------------------------------------------------
extern "C" void kernel_launch(void* const* d_in, const int* in_sizes, int n_in,
                              void* d_out, int out_size)
{
    const float* hs   = (const float*)d_in[0];
    const float* mask = (const float*)d_in[1];
    const float* Wq   = (const float*)d_in[2];
    const float* bq   = (const float*)d_in[3];
    const float* Wqa  = (const float*)d_in[4];
    const float* bqa  = (const float*)d_in[5];
    const float* Wk   = (const float*)d_in[6];
    const float* bk   = (const float*)d_in[7];
    const float* Wt   = (const float*)d_in[8];
    const float* bt   = (const float*)d_in[9];
    float* out = (float*)d_out;

    float *q, *k, *ql, *pq, *pk;
    cudaGetSymbolAddress((void**)&q,  g_q);
    cudaGetSymbolAddress((void**)&k,  g_k);
    cudaGetSymbolAddress((void**)&ql, g_ql);
    cudaGetSymbolAddress((void**)&pq, g_pq);
    cudaGetSymbolAddress((void**)&pk, g_pk);

    cudaFuncSetAttribute(qlogits_kernel,
                         cudaFuncAttributeMaxDynamicSharedMemorySize, 65536);

    dim3 grid(DD / 128, MM / 128);
    dim3 blk(256);

    // q = hs @ Wq + bq ; k = hs @ Wk + bk
    sgemm_kernel<0><<<grid, blk>>>(hs, Wq, bq, q, nullptr, q);
    sgemm_kernel<0><<<grid, blk>>>(hs, Wk, bk, k, nullptr, k);

    // q attention logits
    qlogits_kernel<<<MM / 64, 256, 65536>>>(Wqa, bqa, q, ql);

    // softmax over S + pooled_q, then qk scores + softmax + pooled_k
    softmax_pool_q<<<Bb * HH, 256>>>(mask, ql, q, pq);
    softmax_pool_k<<<Bb * HH, 256>>>(mask, k, pq, pk);

    // out = (pk * q) @ Wt + bt + q
    sgemm_kernel<1><<<grid, blk>>>(q, Wt, bt, out, pk, q);
}

// round 4
// speedup vs baseline: 3.7944x; 3.7944x over previous
#include <cuda_runtime.h>
#include <cuda_bf16.h>
#include <cstdint>
#include <math.h>

#define Bb 8
#define SS 2048
#define DD 1024
#define HH 16
#define DHH 64
#define MM (Bb * SS)
#define SCALE 0.125f

// ---------------- helpers ---------------------------------------------------
__device__ __forceinline__ uint32_t smem_to_u32(const void* p) {
    uint32_t a;
    asm("{ .reg .u64 t; cvta.to.shared.u64 t, %1; cvt.u32.u64 %0, t; }"
        : "=r"(a) : "l"(p));
    return a;
}
__device__ __forceinline__ void ldsm_x4(uint32_t* r, uint32_t addr) {
    asm volatile("ldmatrix.sync.aligned.m8n8.x4.shared.b16 {%0,%1,%2,%3}, [%4];"
        : "=r"(r[0]), "=r"(r[1]), "=r"(r[2]), "=r"(r[3]) : "r"(addr));
}
__device__ __forceinline__ void mma16816(float* c, const uint32_t* a,
                                         uint32_t b0, uint32_t b1) {
    asm volatile("mma.sync.aligned.m16n8k16.row.col.f32.bf16.bf16.f32 "
        "{%0,%1,%2,%3}, {%4,%5,%6,%7}, {%8,%9}, {%0,%1,%2,%3};"
        : "+f"(c[0]), "+f"(c[1]), "+f"(c[2]), "+f"(c[3])
        : "r"(a[0]), "r"(a[1]), "r"(a[2]), "r"(a[3]), "r"(b0), "r"(b1));
}
__device__ __forceinline__ void cp_async16(uint32_t saddr, const void* gaddr) {
    asm volatile("cp.async.cg.shared.global [%0], [%1], 16;"
        :: "r"(saddr), "l"(gaddr));
}
#define CP_COMMIT() asm volatile("cp.async.commit_group;" ::: "memory")
#define CP_WAIT_1() asm volatile("cp.async.wait_group 1;" ::: "memory")
#define CP_WAIT_0() asm volatile("cp.async.wait_group 0;" ::: "memory")

// ---------------- scratch (device globals) ---------------------------------
__device__ float g_q[(size_t)MM * DD];
__device__ float g_k[(size_t)MM * DD];
__device__ float g_ql[(size_t)MM * HH];
__device__ float g_pq[Bb * HH * DHH];
__device__ float g_pk[Bb * HH * DHH];
__device__ __nv_bfloat16 g_hshi[(size_t)MM * DD];
__device__ __nv_bfloat16 g_hslo[(size_t)MM * DD];
__device__ __nv_bfloat16 g_a3hi[(size_t)MM * DD];
__device__ __nv_bfloat16 g_a3lo[(size_t)MM * DD];
__device__ __nv_bfloat16 g_wqhi[DD * DD];
__device__ __nv_bfloat16 g_wqlo[DD * DD];
__device__ __nv_bfloat16 g_wkhi[DD * DD];
__device__ __nv_bfloat16 g_wklo[DD * DD];
__device__ __nv_bfloat16 g_wthi[DD * DD];
__device__ __nv_bfloat16 g_wtlo[DD * DD];

// ---------------- conversion: elementwise split (optional pk multiply) -----
template <int MUL>
__global__ void __launch_bounds__(256)
conv_split(const float* __restrict__ X, const float* __restrict__ pk,
           __nv_bfloat16* __restrict__ hi, __nv_bfloat16* __restrict__ lo)
{
    size_t e = (size_t)blockIdx.x * 256 + threadIdx.x;  // float4 index
    float4 v = ((const float4*)X)[e];
    if (MUL) {
        size_t row = e >> 8;               // e / (DD/4)
        int batch = (int)(row >> 11);      // row / SS
        int col4 = (int)(e & 255);
        float4 p = ((const float4*)(pk + (size_t)batch * DD))[col4];
        v.x *= p.x; v.y *= p.y; v.z *= p.z; v.w *= p.w;
    }
    __nv_bfloat16 hv[4], lv[4];
    float f[4] = {v.x, v.y, v.z, v.w};
#pragma unroll
    for (int i = 0; i < 4; i++) {
        hv[i] = __float2bfloat16(f[i]);
        lv[i] = __float2bfloat16(f[i] - __bfloat162float(hv[i]));
    }
    ((uint2*)hi)[e] = *(uint2*)hv;
    ((uint2*)lo)[e] = *(uint2*)lv;
}

// ---------------- conversion: weight transpose + split ---------------------
// in: W[k][n] fp32 row-major; out: hi/lo[n][k] bf16 (K-major, i.e. W^T)
__global__ void __launch_bounds__(256)
conv_w(const float* __restrict__ W, __nv_bfloat16* __restrict__ hi,
       __nv_bfloat16* __restrict__ lo)
{
    __shared__ float s[32][33];
    int n0 = blockIdx.x * 32, k0 = blockIdx.y * 32;
    int tx = threadIdx.x & 31, ty = threadIdx.x >> 5;  // 32 x 8
#pragma unroll
    for (int i = 0; i < 4; i++) {
        int r = ty + i * 8;
        s[r][tx] = W[(size_t)(k0 + r) * DD + n0 + tx];
    }
    __syncthreads();
#pragma unroll
    for (int i = 0; i < 4; i++) {
        int r = ty + i * 8;                 // output n = n0+r, k = k0+tx
        float v = s[tx][r];
        __nv_bfloat16 h = __float2bfloat16(v);
        hi[(size_t)(n0 + r) * DD + k0 + tx] = h;
        lo[(size_t)(n0 + r) * DD + k0 + tx] =
            __float2bfloat16(v - __bfloat162float(h));
    }
}

// ---------------- HMMA GEMM: C[M,N] = (Ahi+Alo) @ (Bhi+Blo)^T + bias -------
// A: [M,K] K-major bf16 split; B: [N,K] K-major bf16 split (i.e. W^T).
// 128x128x32 tiles, 256 thr, 8 warps of 32x64, cp.async double buffer.
constexpr int PITCH = 80;                  // bytes per 32-elem bf16 row
constexpr int TILEB = 128 * PITCH;         // 10240 bytes per 128x32 tile
constexpr int STAGEB = 4 * TILEB;          // Ahi/Alo/Bhi/Blo per stage
constexpr int SMEMB = 2 * STAGEB;          // 81920

__global__ void __launch_bounds__(256, 2)
gemm_tc(const __nv_bfloat16* __restrict__ Ahi, const __nv_bfloat16* __restrict__ Alo,
        const __nv_bfloat16* __restrict__ Bhi, const __nv_bfloat16* __restrict__ Blo,
        const float* __restrict__ bias, const float* __restrict__ resid,
        float* __restrict__ C, int addResid)
{
    extern __shared__ char smem[];
    const uint32_t sb = smem_to_u32(smem);
    const int tid = threadIdx.x, wid = tid >> 5, lane = tid & 31;
    const int warp_m = wid & 3, warp_n = wid >> 2;
    const int n0 = blockIdx.x * 128;
    const int m0 = blockIdx.y * 128;

    float acc[2][8][4];
#pragma unroll
    for (int i = 0; i < 2; i++)
#pragma unroll
        for (int j = 0; j < 8; j++)
#pragma unroll
            for (int l = 0; l < 4; l++) acc[i][j][l] = 0.0f;

    const __nv_bfloat16* gsrc[4] = {Ahi, Alo, Bhi, Blo};

    auto load_stage = [&](int kt, int st) {
        const int k0 = kt * 32;
#pragma unroll
        for (int tile = 0; tile < 4; tile++) {
            const int rowoff = (tile < 2) ? m0 : n0;
            const __nv_bfloat16* base = gsrc[tile];
#pragma unroll
            for (int h = 0; h < 2; h++) {
                int c = tid + h * 256;           // 0..511
                int row = c >> 2, cc = c & 3;
                uint32_t sa = sb + st * STAGEB + tile * TILEB + row * PITCH + cc * 16;
                cp_async16(sa, base + (size_t)(rowoff + row) * DD + k0 + cc * 8);
            }
        }
    };

    load_stage(0, 0);
    CP_COMMIT();

    for (int kt = 0; kt < 32; kt++) {
        if (kt + 1 < 32) {
            load_stage(kt + 1, (kt + 1) & 1);
            CP_COMMIT();
            CP_WAIT_1();
        } else {
            CP_WAIT_0();
        }
        __syncthreads();

        const uint32_t s0 = sb + (kt & 1) * STAGEB;
        const int rsel = lane & 15;
        const int hsel = (lane >> 4) * 16;

#pragma unroll
        for (int kp = 0; kp < 2; kp++) {
            uint32_t ah[2][4], al[2][4];
            const int ksel = hsel + kp * 32;
#pragma unroll
            for (int mi = 0; mi < 2; mi++) {
                uint32_t off = (uint32_t)(warp_m * 32 + mi * 16 + rsel) * PITCH + ksel;
                ldsm_x4(ah[mi], s0 + off);
                ldsm_x4(al[mi], s0 + TILEB + off);
            }
#pragma unroll
            for (int np = 0; np < 4; np++) {
                uint32_t off = (uint32_t)(warp_n * 64 + np * 16 + rsel) * PITCH + ksel;
                uint32_t bh[4], bl[4];
                ldsm_x4(bh, s0 + 2 * TILEB + off);
                ldsm_x4(bl, s0 + 3 * TILEB + off);
#pragma unroll
                for (int mi = 0; mi < 2; mi++) {
                    mma16816(acc[mi][2 * np],     ah[mi], bh[0], bh[2]);
                    mma16816(acc[mi][2 * np],     ah[mi], bl[0], bl[2]);
                    mma16816(acc[mi][2 * np],     al[mi], bh[0], bh[2]);
                    mma16816(acc[mi][2 * np + 1], ah[mi], bh[1], bh[3]);
                    mma16816(acc[mi][2 * np + 1], ah[mi], bl[1], bl[3]);
                    mma16816(acc[mi][2 * np + 1], al[mi], bh[1], bh[3]);
                }
            }
        }
        __syncthreads();
    }

    // ---------------- epilogue ----------------
#pragma unroll
    for (int mi = 0; mi < 2; mi++) {
        int row = m0 + warp_m * 32 + mi * 16 + (lane >> 2);
#pragma unroll
        for (int ni = 0; ni < 8; ni++) {
            int col = n0 + warp_n * 64 + ni * 8 + (lane & 3) * 2;
            float b0 = __ldg(bias + col), b1 = __ldg(bias + col + 1);
            float2 v0, v1;
            v0.x = acc[mi][ni][0] + b0;  v0.y = acc[mi][ni][1] + b1;
            v1.x = acc[mi][ni][2] + b0;  v1.y = acc[mi][ni][3] + b1;
            if (addResid) {
                float2 r0 = *(const float2*)(resid + (size_t)row * DD + col);
                float2 r1 = *(const float2*)(resid + (size_t)(row + 8) * DD + col);
                v0.x += r0.x; v0.y += r0.y; v1.x += r1.x; v1.y += r1.y;
            }
            *(float2*)(C + (size_t)row * DD + col) = v0;
            *(float2*)(C + (size_t)(row + 8) * DD + col) = v1;
        }
    }
}

// ---------------- q attention logits ---------------------------------------
__global__ void __launch_bounds__(256)
qlogits_kernel(const float* __restrict__ Wqa, const float* __restrict__ bqa,
               const float* __restrict__ q, float* __restrict__ ql)
{
    extern __shared__ float sW[];   // [HH][DD] transposed, 64 KB
    int tid = threadIdx.x;
    for (int i = tid; i < DD * HH; i += 256) {
        int k = i >> 4, h = i & 15;
        sW[h * DD + k] = Wqa[i];
    }
    __syncthreads();

    int warp = tid >> 5, lane = tid & 31;
    for (int rr = 0; rr < 4; rr++) {
        int m = blockIdx.x * 32 + warp * 4 + rr;
        const float* qrow = q + (size_t)m * DD;
        float acc[HH];
#pragma unroll
        for (int h = 0; h < HH; h++) acc[h] = 0.0f;
        for (int k = lane; k < DD; k += 32) {
            float qv = qrow[k];
#pragma unroll
            for (int h = 0; h < HH; h++) acc[h] += qv * sW[h * DD + k];
        }
#pragma unroll
        for (int h = 0; h < HH; h++)
#pragma unroll
            for (int off = 16; off; off >>= 1)
                acc[h] += __shfl_xor_sync(0xffffffffu, acc[h], off);
        if (lane == 0) {
#pragma unroll
            for (int h = 0; h < HH; h++)
                ql[(size_t)m * HH + h] = acc[h] + bqa[h];
        }
    }
}

// ---------------- softmax over S of q logits + pooled_q --------------------
__global__ void __launch_bounds__(1024)
softmax_pool_q(const float* __restrict__ mask, const float* __restrict__ ql,
               const float* __restrict__ q, float* __restrict__ pq)
{
    __shared__ float w[SS];
    __shared__ float red[1024];
    int b = blockIdx.x >> 4, h = blockIdx.x & 15;
    int tid = threadIdx.x;

    float l0 = ql[((size_t)(b * SS + tid)) * HH + h] * SCALE + mask[b * SS + tid];
    float l1 = ql[((size_t)(b * SS + tid + 1024)) * HH + h] * SCALE + mask[b * SS + tid + 1024];

    red[tid] = fmaxf(l0, l1); __syncthreads();
    for (int off = 512; off; off >>= 1) {
        if (tid < off) red[tid] = fmaxf(red[tid], red[tid + off]);
        __syncthreads();
    }
    float mx = red[0];
    __syncthreads();

    float e0 = __expf(l0 - mx), e1 = __expf(l1 - mx);
    w[tid] = e0; w[tid + 1024] = e1;
    red[tid] = e0 + e1; __syncthreads();
    for (int off = 512; off; off >>= 1) {
        if (tid < off) red[tid] += red[tid + off];
        __syncthreads();
    }
    float inv = 1.0f / red[0];
    __syncthreads();

    int g = tid >> 6, dh = tid & 63;       // 16 groups x 64 dh
    const float* qb = q + (size_t)(b * SS) * DD + h * DHH + dh;
    float acc = 0.0f;
    for (int s = g; s < SS; s += 16) acc += w[s] * qb[(size_t)s * DD];
    red[tid] = acc; __syncthreads();
    if (tid < 64) {
        float t = 0.0f;
#pragma unroll
        for (int j = 0; j < 16; j++) t += red[tid + 64 * j];
        pq[blockIdx.x * DHH + tid] = t * inv;
    }
}

// ---------------- qk scores, softmax, pooled_k ------------------------------
__global__ void __launch_bounds__(1024)
softmax_pool_k(const float* __restrict__ mask, const float* __restrict__ kx,
               const float* __restrict__ pq, float* __restrict__ pk)
{
    __shared__ float w[SS];
    __shared__ float red[1024];
    __shared__ float spq[DHH];
    int b = blockIdx.x >> 4, h = blockIdx.x & 15;
    int tid = threadIdx.x;

    if (tid < DHH) spq[tid] = pq[blockIdx.x * DHH + tid];
    __syncthreads();

    int warp = tid >> 5, lane = tid & 31;
    float p0 = spq[lane], p1 = spq[lane + 32];
    const float* kb = kx + (size_t)(b * SS) * DD + h * DHH;
    for (int s = warp; s < SS; s += 32) {
        const float* kr = kb + (size_t)s * DD;
        float part = kr[lane] * p0 + kr[lane + 32] * p1;
#pragma unroll
        for (int off = 16; off; off >>= 1)
            part += __shfl_xor_sync(0xffffffffu, part, off);
        if (lane == 0) w[s] = part * SCALE + mask[b * SS + s];
    }
    __syncthreads();

    float l0 = w[tid], l1 = w[tid + 1024];
    red[tid] = fmaxf(l0, l1); __syncthreads();
    for (int off = 512; off; off >>= 1) {
        if (tid < off) red[tid] = fmaxf(red[tid], red[tid + off]);
        __syncthreads();
    }
    float mx = red[0];
    __syncthreads();

    float e0 = __expf(l0 - mx), e1 = __expf(l1 - mx);
    w[tid] = e0; w[tid + 1024] = e1;
    red[tid] = e0 + e1; __syncthreads();
    for (int off = 512; off; off >>= 1) {
        if (tid < off) red[tid] += red[tid + off];
        __syncthreads();
    }
    float inv = 1.0f / red[0];
    __syncthreads();

    int g = tid >> 6, dh = tid & 63;
    const float* kb2 = kb + dh;
    float acc = 0.0f;
    for (int s = g; s < SS; s += 16) acc += w[s] * kb2[(size_t)s * DD];
    red[tid] = acc; __syncthreads();
    if (tid < 64) {
        float t = 0.0f;
#pragma unroll
        for (int j = 0; j < 16; j++) t += red[tid + 64 * j];
        pk[blockIdx.x * DHH + tid] = t * inv;
    }
}

// ---------------------------------------------------------------------------
extern "C" void kernel_launch(void* const* d_in, const int* in_sizes, int n_in,
                              void* d_out, int out_size)
{
    const float* hs   = (const float*)d_in[0];
    const float* mask = (const float*)d_in[1];
    const float* Wq   = (const float*)d_in[2];
    const float* bq   = (const float*)d_in[3];
    const float* Wqa  = (const float*)d_in[4];
    const float* bqa  = (const float*)d_in[5];
    const float* Wk   = (const float*)d_in[6];
    const float* bk   = (const float*)d_in[7];
    const float* Wt   = (const float*)d_in[8];
    const float* bt   = (const float*)d_in[9];
    float* out = (float*)d_out;

    float *q, *k, *ql, *pq, *pk;
    __nv_bfloat16 *hshi, *hslo, *a3hi, *a3lo;
    __nv_bfloat16 *wqhi, *wqlo, *wkhi, *wklo, *wthi, *wtlo;
    cudaGetSymbolAddress((void**)&q,  g_q);
    cudaGetSymbolAddress((void**)&k,  g_k);
    cudaGetSymbolAddress((void**)&ql, g_ql);
    cudaGetSymbolAddress((void**)&pq, g_pq);
    cudaGetSymbolAddress((void**)&pk, g_pk);
    cudaGetSymbolAddress((void**)&hshi, g_hshi);
    cudaGetSymbolAddress((void**)&hslo, g_hslo);
    cudaGetSymbolAddress((void**)&a3hi, g_a3hi);
    cudaGetSymbolAddress((void**)&a3lo, g_a3lo);
    cudaGetSymbolAddress((void**)&wqhi, g_wqhi);
    cudaGetSymbolAddress((void**)&wqlo, g_wqlo);
    cudaGetSymbolAddress((void**)&wkhi, g_wkhi);
    cudaGetSymbolAddress((void**)&wklo, g_wklo);
    cudaGetSymbolAddress((void**)&wthi, g_wthi);
    cudaGetSymbolAddress((void**)&wtlo, g_wtlo);

    cudaFuncSetAttribute(qlogits_kernel,
                         cudaFuncAttributeMaxDynamicSharedMemorySize, 65536);
    cudaFuncSetAttribute(gemm_tc,
                         cudaFuncAttributeMaxDynamicSharedMemorySize, SMEMB);

    const int conv_blocks = (MM * DD / 4) / 256;   // 16384
    dim3 wgrid(DD / 32, DD / 32);
    dim3 ggrid(DD / 128, MM / 128);                // (8, 128)

    // conversions
    conv_split<0><<<conv_blocks, 256>>>(hs, nullptr, hshi, hslo);
    conv_w<<<wgrid, 256>>>(Wq, wqhi, wqlo);
    conv_w<<<wgrid, 256>>>(Wk, wkhi, wklo);
    conv_w<<<wgrid, 256>>>(Wt, wthi, wtlo);

    // q = hs @ Wq + bq ; k = hs @ Wk + bk  (HMMA, bf16 3-term split)
    gemm_tc<<<ggrid, 256, SMEMB>>>(hshi, hslo, wqhi, wqlo, bq, q, q, 0);
    gemm_tc<<<ggrid, 256, SMEMB>>>(hshi, hslo, wkhi, wklo, bk, k, k, 0);

    // q attention logits, softmax pools
    qlogits_kernel<<<MM / 32, 256, 65536>>>(Wqa, bqa, q, ql);
    softmax_pool_q<<<Bb * HH, 1024>>>(mask, ql, q, pq);
    softmax_pool_k<<<Bb * HH, 1024>>>(mask, k, pq, pk);

    // a3 = q * pk (broadcast over s), split to bf16
    conv_split<1><<<conv_blocks, 256>>>(q, pk, a3hi, a3lo);

    // out = a3 @ Wt + bt + q
    gemm_tc<<<ggrid, 256, SMEMB>>>(a3hi, a3lo, wthi, wtlo, bt, q, out, 1);
}

// round 5
// speedup vs baseline: 4.9837x; 1.3134x over previous
#include <cuda_runtime.h>
#include <cuda_fp16.h>
#include <cstdint>
#include <math.h>

#define Bb 8
#define SS 2048
#define DD 1024
#define HH 16
#define DHH 64
#define MM (Bb * SS)
#define SCALE 0.125f

// ---------------- helpers ---------------------------------------------------
__device__ __forceinline__ uint32_t smem_to_u32(const void* p) {
    uint32_t a;
    asm("{ .reg .u64 t; cvta.to.shared.u64 t, %1; cvt.u32.u64 %0, t; }"
        : "=r"(a) : "l"(p));
    return a;
}
__device__ __forceinline__ void ldsm_x4(uint32_t* r, uint32_t addr) {
    asm volatile("ldmatrix.sync.aligned.m8n8.x4.shared.b16 {%0,%1,%2,%3}, [%4];"
        : "=r"(r[0]), "=r"(r[1]), "=r"(r[2]), "=r"(r[3]) : "r"(addr));
}
__device__ __forceinline__ void mma16816(float* c, const uint32_t* a,
                                         uint32_t b0, uint32_t b1) {
    asm volatile("mma.sync.aligned.m16n8k16.row.col.f32.f16.f16.f32 "
        "{%0,%1,%2,%3}, {%4,%5,%6,%7}, {%8,%9}, {%0,%1,%2,%3};"
        : "+f"(c[0]), "+f"(c[1]), "+f"(c[2]), "+f"(c[3])
        : "r"(a[0]), "r"(a[1]), "r"(a[2]), "r"(a[3]), "r"(b0), "r"(b1));
}
__device__ __forceinline__ void cp_async16(uint32_t saddr, const void* gaddr) {
    asm volatile("cp.async.cg.shared.global [%0], [%1], 16;"
        :: "r"(saddr), "l"(gaddr));
}
#define CP_COMMIT() asm volatile("cp.async.commit_group;" ::: "memory")
#define CP_WAIT_1() asm volatile("cp.async.wait_group 1;" ::: "memory")
#define CP_WAIT_0() asm volatile("cp.async.wait_group 0;" ::: "memory")

// ---------------- scratch (device globals) ---------------------------------
__device__ float g_q[(size_t)MM * DD];
__device__ float g_k[(size_t)MM * DD];
__device__ float g_ql[(size_t)MM * HH];
__device__ float g_pq[Bb * HH * DHH];
__device__ float g_pk[Bb * HH * DHH];
__device__ __half g_hshi[(size_t)MM * DD];
__device__ __half g_hslo[(size_t)MM * DD];
__device__ __half g_a3hi[(size_t)MM * DD];
__device__ __half g_a3lo[(size_t)MM * DD];
__device__ __half g_wq[DD * DD];
__device__ __half g_wk[DD * DD];
__device__ __half g_wt[DD * DD];

// ---------------- conversion: elementwise split (optional pk multiply) -----
template <int MUL>
__global__ void __launch_bounds__(256)
conv_split(const float* __restrict__ X, const float* __restrict__ pk,
           __half* __restrict__ hi, __half* __restrict__ lo)
{
    size_t e = (size_t)blockIdx.x * 256 + threadIdx.x;  // float4 index
    float4 v = ((const float4*)X)[e];
    if (MUL) {
        size_t row = e >> 8;               // e / (DD/4)
        int batch = (int)(row >> 11);      // row / SS
        int col4 = (int)(e & 255);
        float4 p = ((const float4*)(pk + (size_t)batch * DD))[col4];
        v.x *= p.x; v.y *= p.y; v.z *= p.z; v.w *= p.w;
    }
    __half hv[4], lv[4];
    float f[4] = {v.x, v.y, v.z, v.w};
#pragma unroll
    for (int i = 0; i < 4; i++) {
        hv[i] = __float2half_rn(f[i]);
        lv[i] = __float2half_rn(f[i] - __half2float(hv[i]));
    }
    ((uint2*)hi)[e] = *(uint2*)hv;
    ((uint2*)lo)[e] = *(uint2*)lv;
}

// ---------------- conversion: weight transpose to fp16 ---------------------
// in: W[k][n] fp32 row-major; out: wt[n][k] fp16 (K-major, i.e. W^T)
__global__ void __launch_bounds__(256)
conv_w(const float* __restrict__ W, __half* __restrict__ wt)
{
    __shared__ float s[32][33];
    int n0 = blockIdx.x * 32, k0 = blockIdx.y * 32;
    int tx = threadIdx.x & 31, ty = threadIdx.x >> 5;  // 32 x 8
#pragma unroll
    for (int i = 0; i < 4; i++) {
        int r = ty + i * 8;
        s[r][tx] = W[(size_t)(k0 + r) * DD + n0 + tx];
    }
    __syncthreads();
#pragma unroll
    for (int i = 0; i < 4; i++) {
        int r = ty + i * 8;                 // output n = n0+r, k = k0+tx
        wt[(size_t)(n0 + r) * DD + k0 + tx] = __float2half_rn(s[tx][r]);
    }
}

// ---------------- HMMA GEMM: C[M,N] = (Ahi+Alo) @ B^T + bias ---------------
// A: [M,K] K-major fp16 split; B: [N,K] K-major fp16 (i.e. W^T).
// 128x128x32 tiles, 256 thr, 8 warps of 32x64, cp.async double buffer.
constexpr int PITCH = 80;                  // bytes per 32-elem fp16 row
constexpr int TILEB = 128 * PITCH;         // 10240 bytes per 128x32 tile
constexpr int STAGEB = 3 * TILEB;          // Ahi/Alo/B per stage = 30720
constexpr int SMEMB = 2 * STAGEB;          // 61440

__global__ void __launch_bounds__(256, 2)
gemm_tc(const __half* __restrict__ Ahi, const __half* __restrict__ Alo,
        const __half* __restrict__ Bw,
        const float* __restrict__ bias, const float* __restrict__ resid,
        float* __restrict__ C, int addResid)
{
    extern __shared__ char smem[];
    const uint32_t sb = smem_to_u32(smem);
    const int tid = threadIdx.x, wid = tid >> 5, lane = tid & 31;
    const int warp_m = wid & 3, warp_n = wid >> 2;
    const int n0 = blockIdx.x * 128;
    const int m0 = blockIdx.y * 128;

    float acc[2][8][4];
#pragma unroll
    for (int i = 0; i < 2; i++)
#pragma unroll
        for (int j = 0; j < 8; j++)
#pragma unroll
            for (int l = 0; l < 4; l++) acc[i][j][l] = 0.0f;

    const __half* gsrc[3] = {Ahi, Alo, Bw};

    auto load_stage = [&](int kt, int st) {
        const int k0 = kt * 32;
#pragma unroll
        for (int tile = 0; tile < 3; tile++) {
            const int rowoff = (tile < 2) ? m0 : n0;
            const __half* base = gsrc[tile];
#pragma unroll
            for (int h = 0; h < 2; h++) {
                int c = tid + h * 256;           // 0..511
                int row = c >> 2, cc = c & 3;
                uint32_t sa = sb + st * STAGEB + tile * TILEB + row * PITCH + cc * 16;
                cp_async16(sa, base + (size_t)(rowoff + row) * DD + k0 + cc * 8);
            }
        }
    };

    load_stage(0, 0);
    CP_COMMIT();

    for (int kt = 0; kt < 32; kt++) {
        if (kt + 1 < 32) {
            load_stage(kt + 1, (kt + 1) & 1);
            CP_COMMIT();
            CP_WAIT_1();
        } else {
            CP_WAIT_0();
        }
        __syncthreads();

        const uint32_t s0 = sb + (kt & 1) * STAGEB;
        const int rsel = lane & 15;
        const int hsel = (lane >> 4) * 16;

#pragma unroll
        for (int kp = 0; kp < 2; kp++) {
            uint32_t ah[2][4], al[2][4];
            const int ksel = hsel + kp * 32;
#pragma unroll
            for (int mi = 0; mi < 2; mi++) {
                uint32_t off = (uint32_t)(warp_m * 32 + mi * 16 + rsel) * PITCH + ksel;
                ldsm_x4(ah[mi], s0 + off);
                ldsm_x4(al[mi], s0 + TILEB + off);
            }
#pragma unroll
            for (int np = 0; np < 4; np++) {
                uint32_t off = (uint32_t)(warp_n * 64 + np * 16 + rsel) * PITCH + ksel;
                uint32_t bh[4];
                ldsm_x4(bh, s0 + 2 * TILEB + off);
#pragma unroll
                for (int mi = 0; mi < 2; mi++) {
                    mma16816(acc[mi][2 * np],     ah[mi], bh[0], bh[2]);
                    mma16816(acc[mi][2 * np],     al[mi], bh[0], bh[2]);
                    mma16816(acc[mi][2 * np + 1], ah[mi], bh[1], bh[3]);
                    mma16816(acc[mi][2 * np + 1], al[mi], bh[1], bh[3]);
                }
            }
        }
        __syncthreads();
    }

    // ---------------- epilogue ----------------
#pragma unroll
    for (int mi = 0; mi < 2; mi++) {
        int row = m0 + warp_m * 32 + mi * 16 + (lane >> 2);
#pragma unroll
        for (int ni = 0; ni < 8; ni++) {
            int col = n0 + warp_n * 64 + ni * 8 + (lane & 3) * 2;
            float b0 = __ldg(bias + col), b1 = __ldg(bias + col + 1);
            float2 v0, v1;
            v0.x = acc[mi][ni][0] + b0;  v0.y = acc[mi][ni][1] + b1;
            v1.x = acc[mi][ni][2] + b0;  v1.y = acc[mi][ni][3] + b1;
            if (addResid) {
                float2 r0 = *(const float2*)(resid + (size_t)row * DD + col);
                float2 r1 = *(const float2*)(resid + (size_t)(row + 8) * DD + col);
                v0.x += r0.x; v0.y += r0.y; v1.x += r1.x; v1.y += r1.y;
            }
            *(float2*)(C + (size_t)row * DD + col) = v0;
            *(float2*)(C + (size_t)(row + 8) * DD + col) = v1;
        }
    }
}

// ---------------- q attention logits ---------------------------------------
__global__ void __launch_bounds__(256)
qlogits_kernel(const float* __restrict__ Wqa, const float* __restrict__ bqa,
               const float* __restrict__ q, float* __restrict__ ql)
{
    extern __shared__ float sW[];   // [HH][DD] transposed, 64 KB
    int tid = threadIdx.x;
    for (int i = tid; i < DD * HH; i += 256) {
        int k = i >> 4, h = i & 15;
        sW[h * DD + k] = Wqa[i];
    }
    __syncthreads();

    int warp = tid >> 5, lane = tid & 31;
    for (int rr = 0; rr < 4; rr++) {
        int m = blockIdx.x * 32 + warp * 4 + rr;
        const float* qrow = q + (size_t)m * DD;
        float acc[HH];
#pragma unroll
        for (int h = 0; h < HH; h++) acc[h] = 0.0f;
        for (int k = lane; k < DD; k += 32) {
            float qv = qrow[k];
#pragma unroll
            for (int h = 0; h < HH; h++) acc[h] += qv * sW[h * DD + k];
        }
#pragma unroll
        for (int h = 0; h < HH; h++)
#pragma unroll
            for (int off = 16; off; off >>= 1)
                acc[h] += __shfl_xor_sync(0xffffffffu, acc[h], off);
        if (lane == 0) {
#pragma unroll
            for (int h = 0; h < HH; h++)
                ql[(size_t)m * HH + h] = acc[h] + bqa[h];
        }
    }
}

// ---------------- softmax over S of q logits + pooled_q --------------------
__global__ void __launch_bounds__(1024)
softmax_pool_q(const float* __restrict__ mask, const float* __restrict__ ql,
               const float* __restrict__ q, float* __restrict__ pq)
{
    __shared__ float w[SS];
    __shared__ float red[1024];
    int b = blockIdx.x >> 4, h = blockIdx.x & 15;
    int tid = threadIdx.x;

    float l0 = ql[((size_t)(b * SS + tid)) * HH + h] * SCALE + mask[b * SS + tid];
    float l1 = ql[((size_t)(b * SS + tid + 1024)) * HH + h] * SCALE + mask[b * SS + tid + 1024];

    red[tid] = fmaxf(l0, l1); __syncthreads();
    for (int off = 512; off; off >>= 1) {
        if (tid < off) red[tid] = fmaxf(red[tid], red[tid + off]);
        __syncthreads();
    }
    float mx = red[0];
    __syncthreads();

    float e0 = __expf(l0 - mx), e1 = __expf(l1 - mx);
    w[tid] = e0; w[tid + 1024] = e1;
    red[tid] = e0 + e1; __syncthreads();
    for (int off = 512; off; off >>= 1) {
        if (tid < off) red[tid] += red[tid + off];
        __syncthreads();
    }
    float inv = 1.0f / red[0];
    __syncthreads();

    int g = tid >> 6, dh = tid & 63;       // 16 groups x 64 dh
    const float* qb = q + (size_t)(b * SS) * DD + h * DHH + dh;
    float acc = 0.0f;
    for (int s = g; s < SS; s += 16) acc += w[s] * qb[(size_t)s * DD];
    red[tid] = acc; __syncthreads();
    if (tid < 64) {
        float t = 0.0f;
#pragma unroll
        for (int j = 0; j < 16; j++) t += red[tid + 64 * j];
        pq[blockIdx.x * DHH + tid] = t * inv;
    }
}

// ---------------- qk scores, softmax, pooled_k ------------------------------
__global__ void __launch_bounds__(1024)
softmax_pool_k(const float* __restrict__ mask, const float* __restrict__ kx,
               const float* __restrict__ pq, float* __restrict__ pk)
{
    __shared__ float w[SS];
    __shared__ float red[1024];
    __shared__ float spq[DHH];
    int b = blockIdx.x >> 4, h = blockIdx.x & 15;
    int tid = threadIdx.x;

    if (tid < DHH) spq[tid] = pq[blockIdx.x * DHH + tid];
    __syncthreads();

    int warp = tid >> 5, lane = tid & 31;
    float p0 = spq[lane], p1 = spq[lane + 32];
    const float* kb = kx + (size_t)(b * SS) * DD + h * DHH;
    for (int s = warp; s < SS; s += 32) {
        const float* kr = kb + (size_t)s * DD;
        float part = kr[lane] * p0 + kr[lane + 32] * p1;
#pragma unroll
        for (int off = 16; off; off >>= 1)
            part += __shfl_xor_sync(0xffffffffu, part, off);
        if (lane == 0) w[s] = part * SCALE + mask[b * SS + s];
    }
    __syncthreads();

    float l0 = w[tid], l1 = w[tid + 1024];
    red[tid] = fmaxf(l0, l1); __syncthreads();
    for (int off = 512; off; off >>= 1) {
        if (tid < off) red[tid] = fmaxf(red[tid], red[tid + off]);
        __syncthreads();
    }
    float mx = red[0];
    __syncthreads();

    float e0 = __expf(l0 - mx), e1 = __expf(l1 - mx);
    w[tid] = e0; w[tid + 1024] = e1;
    red[tid] = e0 + e1; __syncthreads();
    for (int off = 512; off; off >>= 1) {
        if (tid < off) red[tid] += red[tid + off];
        __syncthreads();
    }
    float inv = 1.0f / red[0];
    __syncthreads();

    int g = tid >> 6, dh = tid & 63;
    const float* kb2 = kb + dh;
    float acc = 0.0f;
    for (int s = g; s < SS; s += 16) acc += w[s] * kb2[(size_t)s * DD];
    red[tid] = acc; __syncthreads();
    if (tid < 64) {
        float t = 0.0f;
#pragma unroll
        for (int j = 0; j < 16; j++) t += red[tid + 64 * j];
        pk[blockIdx.x * DHH + tid] = t * inv;
    }
}

// ---------------------------------------------------------------------------
extern "C" void kernel_launch(void* const* d_in, const int* in_sizes, int n_in,
                              void* d_out, int out_size)
{
    const float* hs   = (const float*)d_in[0];
    const float* mask = (const float*)d_in[1];
    const float* Wq   = (const float*)d_in[2];
    const float* bq   = (const float*)d_in[3];
    const float* Wqa  = (const float*)d_in[4];
    const float* bqa  = (const float*)d_in[5];
    const float* Wk   = (const float*)d_in[6];
    const float* bk   = (const float*)d_in[7];
    const float* Wt   = (const float*)d_in[8];
    const float* bt   = (const float*)d_in[9];
    float* out = (float*)d_out;

    float *q, *k, *ql, *pq, *pk;
    __half *hshi, *hslo, *a3hi, *a3lo, *wq, *wk, *wt;
    cudaGetSymbolAddress((void**)&q,  g_q);
    cudaGetSymbolAddress((void**)&k,  g_k);
    cudaGetSymbolAddress((void**)&ql, g_ql);
    cudaGetSymbolAddress((void**)&pq, g_pq);
    cudaGetSymbolAddress((void**)&pk, g_pk);
    cudaGetSymbolAddress((void**)&hshi, g_hshi);
    cudaGetSymbolAddress((void**)&hslo, g_hslo);
    cudaGetSymbolAddress((void**)&a3hi, g_a3hi);
    cudaGetSymbolAddress((void**)&a3lo, g_a3lo);
    cudaGetSymbolAddress((void**)&wq, g_wq);
    cudaGetSymbolAddress((void**)&wk, g_wk);
    cudaGetSymbolAddress((void**)&wt, g_wt);

    cudaFuncSetAttribute(qlogits_kernel,
                         cudaFuncAttributeMaxDynamicSharedMemorySize, 65536);
    cudaFuncSetAttribute(gemm_tc,
                         cudaFuncAttributeMaxDynamicSharedMemorySize, SMEMB);

    const int conv_blocks = (MM * DD / 4) / 256;   // 16384
    dim3 wgrid(DD / 32, DD / 32);
    dim3 ggrid(DD / 128, MM / 128);                // (8, 128)

    // conversions
    conv_split<0><<<conv_blocks, 256>>>(hs, nullptr, hshi, hslo);
    conv_w<<<wgrid, 256>>>(Wq, wq);
    conv_w<<<wgrid, 256>>>(Wk, wk);
    conv_w<<<wgrid, 256>>>(Wt, wt);

    // q = hs @ Wq + bq ; k = hs @ Wk + bk  (HMMA, fp16 2-term split)
    gemm_tc<<<ggrid, 256, SMEMB>>>(hshi, hslo, wq, bq, q, q, 0);
    gemm_tc<<<ggrid, 256, SMEMB>>>(hshi, hslo, wk, bk, k, k, 0);

    // q attention logits, softmax pools
    qlogits_kernel<<<MM / 32, 256, 65536>>>(Wqa, bqa, q, ql);
    softmax_pool_q<<<Bb * HH, 1024>>>(mask, ql, q, pq);
    softmax_pool_k<<<Bb * HH, 1024>>>(mask, k, pq, pk);

    // a3 = q * pk (broadcast over s), split to fp16
    conv_split<1><<<conv_blocks, 256>>>(q, pk, a3hi, a3lo);

    // out = a3 @ Wt + bt + q
    gemm_tc<<<ggrid, 256, SMEMB>>>(a3hi, a3lo, wt, bt, q, out, 1);
}

// round 6
// speedup vs baseline: 7.2936x; 1.4635x over previous
#include <cuda_runtime.h>
#include <cuda_fp16.h>
#include <cstdint>
#include <math.h>

#define Bb 8
#define SS 2048
#define DD 1024
#define HH 16
#define DHH 64
#define MM (Bb * SS)
#define SCALE 0.125f

// ---------------- helpers ---------------------------------------------------
__device__ __forceinline__ uint32_t smem_to_u32(const void* p) {
    uint32_t a;
    asm("{ .reg .u64 t; cvta.to.shared.u64 t, %1; cvt.u32.u64 %0, t; }"
        : "=r"(a) : "l"(p));
    return a;
}
__device__ __forceinline__ void ldsm_x4(uint32_t* r, uint32_t addr) {
    asm volatile("ldmatrix.sync.aligned.m8n8.x4.shared.b16 {%0,%1,%2,%3}, [%4];"
        : "=r"(r[0]), "=r"(r[1]), "=r"(r[2]), "=r"(r[3]) : "r"(addr));
}
__device__ __forceinline__ void mma16816(float* c, const uint32_t* a,
                                         uint32_t b0, uint32_t b1) {
    asm volatile("mma.sync.aligned.m16n8k16.row.col.f32.f16.f16.f32 "
        "{%0,%1,%2,%3}, {%4,%5,%6,%7}, {%8,%9}, {%0,%1,%2,%3};"
        : "+f"(c[0]), "+f"(c[1]), "+f"(c[2]), "+f"(c[3])
        : "r"(a[0]), "r"(a[1]), "r"(a[2]), "r"(a[3]), "r"(b0), "r"(b1));
}
__device__ __forceinline__ void cp_async16(uint32_t saddr, const void* gaddr) {
    asm volatile("cp.async.cg.shared.global [%0], [%1], 16;"
        :: "r"(saddr), "l"(gaddr));
}
#define CP_COMMIT() asm volatile("cp.async.commit_group;" ::: "memory")
#define CP_WAIT_2() asm volatile("cp.async.wait_group 2;" ::: "memory")
#define CP_WAIT_1() asm volatile("cp.async.wait_group 1;" ::: "memory")
#define CP_WAIT_0() asm volatile("cp.async.wait_group 0;" ::: "memory")

// ---------------- scratch (device globals) ---------------------------------
__device__ float g_q[(size_t)MM * DD];
__device__ float g_k[(size_t)MM * DD];
__device__ float g_ql[(size_t)MM * HH];
__device__ float g_pq[Bb * HH * DHH];
__device__ float g_pk[Bb * HH * DHH];
__device__ __half g_hsh[(size_t)MM * DD];
__device__ __half g_a3h[(size_t)MM * DD];
__device__ __half g_wq[DD * DD];
__device__ __half g_wk[DD * DD];
__device__ __half g_wt[DD * DD];

// ---------------- conversion: fp32 -> fp16 (optional pk multiply) ----------
template <int MUL>
__global__ void __launch_bounds__(256)
conv_half(const float* __restrict__ X, const float* __restrict__ pk,
          __half* __restrict__ out)
{
    size_t e = (size_t)blockIdx.x * 256 + threadIdx.x;  // float4 index
    float4 v = ((const float4*)X)[e];
    if (MUL) {
        size_t row = e >> 8;               // e / (DD/4)
        int batch = (int)(row >> 11);      // row / SS
        int col4 = (int)(e & 255);
        float4 p = ((const float4*)(pk + (size_t)batch * DD))[col4];
        v.x *= p.x; v.y *= p.y; v.z *= p.z; v.w *= p.w;
    }
    __half hv[4];
    hv[0] = __float2half_rn(v.x); hv[1] = __float2half_rn(v.y);
    hv[2] = __float2half_rn(v.z); hv[3] = __float2half_rn(v.w);
    ((uint2*)out)[e] = *(uint2*)hv;
}

// ---------------- conversion: weight transpose to fp16 ---------------------
// in: W[k][n] fp32 row-major; out: wt[n][k] fp16 (K-major, i.e. W^T)
__global__ void __launch_bounds__(256)
conv_w(const float* __restrict__ W, __half* __restrict__ wt)
{
    __shared__ float s[32][33];
    int n0 = blockIdx.x * 32, k0 = blockIdx.y * 32;
    int tx = threadIdx.x & 31, ty = threadIdx.x >> 5;  // 32 x 8
#pragma unroll
    for (int i = 0; i < 4; i++) {
        int r = ty + i * 8;
        s[r][tx] = W[(size_t)(k0 + r) * DD + n0 + tx];
    }
    __syncthreads();
#pragma unroll
    for (int i = 0; i < 4; i++) {
        int r = ty + i * 8;                 // output n = n0+r, k = k0+tx
        wt[(size_t)(n0 + r) * DD + k0 + tx] = __float2half_rn(s[tx][r]);
    }
}

// ---------------- HMMA GEMM: C[M,N] = A @ B^T + bias -----------------------
// A: [M,K] K-major fp16; B: [N,K] K-major fp16 (i.e. W^T).
// 128x128x32 tiles, 256 thr, 8 warps of 32x64, cp.async 3-stage ring.
constexpr int PITCH = 80;                  // bytes per 32-elem fp16 row
constexpr int TILEB = 128 * PITCH;         // 10240 bytes per 128x32 tile
constexpr int STAGEB = 2 * TILEB;          // A/B per stage = 20480
constexpr int SMEMB = 3 * STAGEB;          // 61440
constexpr int NKT = 32;

__global__ void __launch_bounds__(256, 2)
gemm_tc(const __half* __restrict__ Ah, const __half* __restrict__ Bw,
        const float* __restrict__ bias, const float* __restrict__ resid,
        float* __restrict__ C, int addResid)
{
    extern __shared__ char smem[];
    const uint32_t sb = smem_to_u32(smem);
    const int tid = threadIdx.x, wid = tid >> 5, lane = tid & 31;
    const int warp_m = wid & 3, warp_n = wid >> 2;
    const int n0 = blockIdx.x * 128;
    const int m0 = blockIdx.y * 128;

    float acc[2][8][4];
#pragma unroll
    for (int i = 0; i < 2; i++)
#pragma unroll
        for (int j = 0; j < 8; j++)
#pragma unroll
            for (int l = 0; l < 4; l++) acc[i][j][l] = 0.0f;

    auto load_stage = [&](int kt, int st) {
        const int k0 = kt * 32;
#pragma unroll
        for (int tile = 0; tile < 2; tile++) {
            const int rowoff = (tile == 0) ? m0 : n0;
            const __half* base = (tile == 0) ? Ah : Bw;
#pragma unroll
            for (int h = 0; h < 2; h++) {
                int c = tid + h * 256;           // 0..511
                int row = c >> 2, cc = c & 3;
                uint32_t sa = sb + st * STAGEB + tile * TILEB + row * PITCH + cc * 16;
                cp_async16(sa, base + (size_t)(rowoff + row) * DD + k0 + cc * 8);
            }
        }
    };

    load_stage(0, 0); CP_COMMIT();
    load_stage(1, 1); CP_COMMIT();

    for (int kt = 0; kt < NKT; kt++) {
        if (kt + 2 < NKT) {
            load_stage(kt + 2, (kt + 2) % 3);
            CP_COMMIT();
            CP_WAIT_2();
        } else if (kt + 1 < NKT) {
            CP_WAIT_1();
        } else {
            CP_WAIT_0();
        }
        __syncthreads();

        const uint32_t s0 = sb + (kt % 3) * STAGEB;
        const int rsel = lane & 15;
        const int hsel = (lane >> 4) * 16;

#pragma unroll
        for (int kp = 0; kp < 2; kp++) {
            uint32_t ah[2][4];
            const int ksel = hsel + kp * 32;
#pragma unroll
            for (int mi = 0; mi < 2; mi++) {
                uint32_t off = (uint32_t)(warp_m * 32 + mi * 16 + rsel) * PITCH + ksel;
                ldsm_x4(ah[mi], s0 + off);
            }
#pragma unroll
            for (int np = 0; np < 4; np++) {
                uint32_t off = (uint32_t)(warp_n * 64 + np * 16 + rsel) * PITCH + ksel;
                uint32_t bh[4];
                ldsm_x4(bh, s0 + TILEB + off);
#pragma unroll
                for (int mi = 0; mi < 2; mi++) {
                    mma16816(acc[mi][2 * np],     ah[mi], bh[0], bh[2]);
                    mma16816(acc[mi][2 * np + 1], ah[mi], bh[1], bh[3]);
                }
            }
        }
        __syncthreads();
    }

    // ---------------- epilogue ----------------
#pragma unroll
    for (int mi = 0; mi < 2; mi++) {
        int row = m0 + warp_m * 32 + mi * 16 + (lane >> 2);
#pragma unroll
        for (int ni = 0; ni < 8; ni++) {
            int col = n0 + warp_n * 64 + ni * 8 + (lane & 3) * 2;
            float b0 = __ldg(bias + col), b1 = __ldg(bias + col + 1);
            float2 v0, v1;
            v0.x = acc[mi][ni][0] + b0;  v0.y = acc[mi][ni][1] + b1;
            v1.x = acc[mi][ni][2] + b0;  v1.y = acc[mi][ni][3] + b1;
            if (addResid) {
                float2 r0 = *(const float2*)(resid + (size_t)row * DD + col);
                float2 r1 = *(const float2*)(resid + (size_t)(row + 8) * DD + col);
                v0.x += r0.x; v0.y += r0.y; v1.x += r1.x; v1.y += r1.y;
            }
            *(float2*)(C + (size_t)row * DD + col) = v0;
            *(float2*)(C + (size_t)(row + 8) * DD + col) = v1;
        }
    }
}

// ---------------- q attention logits ---------------------------------------
__global__ void __launch_bounds__(256)
qlogits_kernel(const float* __restrict__ Wqa, const float* __restrict__ bqa,
               const float* __restrict__ q, float* __restrict__ ql)
{
    extern __shared__ float sW[];   // [HH][DD] transposed, 64 KB
    int tid = threadIdx.x;
    for (int i = tid; i < DD * HH; i += 256) {
        int k = i >> 4, h = i & 15;
        sW[h * DD + k] = Wqa[i];
    }
    __syncthreads();

    int warp = tid >> 5, lane = tid & 31;
    for (int rr = 0; rr < 4; rr++) {
        int m = blockIdx.x * 32 + warp * 4 + rr;
        const float* qrow = q + (size_t)m * DD;
        float acc[HH];
#pragma unroll
        for (int h = 0; h < HH; h++) acc[h] = 0.0f;
        for (int k = lane; k < DD; k += 32) {
            float qv = qrow[k];
#pragma unroll
            for (int h = 0; h < HH; h++) acc[h] += qv * sW[h * DD + k];
        }
#pragma unroll
        for (int h = 0; h < HH; h++)
#pragma unroll
            for (int off = 16; off; off >>= 1)
                acc[h] += __shfl_xor_sync(0xffffffffu, acc[h], off);
        if (lane == 0) {
#pragma unroll
            for (int h = 0; h < HH; h++)
                ql[(size_t)m * HH + h] = acc[h] + bqa[h];
        }
    }
}

// ---------------- softmax over S of q logits + pooled_q --------------------
__global__ void __launch_bounds__(1024)
softmax_pool_q(const float* __restrict__ mask, const float* __restrict__ ql,
               const float* __restrict__ q, float* __restrict__ pq)
{
    __shared__ float w[SS];
    __shared__ float red[1024];
    int b = blockIdx.x >> 4, h = blockIdx.x & 15;
    int tid = threadIdx.x;

    float l0 = ql[((size_t)(b * SS + tid)) * HH + h] * SCALE + mask[b * SS + tid];
    float l1 = ql[((size_t)(b * SS + tid + 1024)) * HH + h] * SCALE + mask[b * SS + tid + 1024];

    red[tid] = fmaxf(l0, l1); __syncthreads();
    for (int off = 512; off; off >>= 1) {
        if (tid < off) red[tid] = fmaxf(red[tid], red[tid + off]);
        __syncthreads();
    }
    float mx = red[0];
    __syncthreads();

    float e0 = __expf(l0 - mx), e1 = __expf(l1 - mx);
    w[tid] = e0; w[tid + 1024] = e1;
    red[tid] = e0 + e1; __syncthreads();
    for (int off = 512; off; off >>= 1) {
        if (tid < off) red[tid] += red[tid + off];
        __syncthreads();
    }
    float inv = 1.0f / red[0];
    __syncthreads();

    int g = tid >> 6, dh = tid & 63;       // 16 groups x 64 dh
    const float* qb = q + (size_t)(b * SS) * DD + h * DHH + dh;
    float acc = 0.0f;
    for (int s = g; s < SS; s += 16) acc += w[s] * qb[(size_t)s * DD];
    red[tid] = acc; __syncthreads();
    if (tid < 64) {
        float t = 0.0f;
#pragma unroll
        for (int j = 0; j < 16; j++) t += red[tid + 64 * j];
        pq[blockIdx.x * DHH + tid] = t * inv;
    }
}

// ---------------- qk scores, softmax, pooled_k ------------------------------
__global__ void __launch_bounds__(1024)
softmax_pool_k(const float* __restrict__ mask, const float* __restrict__ kx,
               const float* __restrict__ pq, float* __restrict__ pk)
{
    __shared__ float w[SS];
    __shared__ float red[1024];
    __shared__ float spq[DHH];
    int b = blockIdx.x >> 4, h = blockIdx.x & 15;
    int tid = threadIdx.x;

    if (tid < DHH) spq[tid] = pq[blockIdx.x * DHH + tid];
    __syncthreads();

    int warp = tid >> 5, lane = tid & 31;
    float p0 = spq[lane], p1 = spq[lane + 32];
    const float* kb = kx + (size_t)(b * SS) * DD + h * DHH;
    for (int s = warp; s < SS; s += 32) {
        const float* kr = kb + (size_t)s * DD;
        float part = kr[lane] * p0 + kr[lane + 32] * p1;
#pragma unroll
        for (int off = 16; off; off >>= 1)
            part += __shfl_xor_sync(0xffffffffu, part, off);
        if (lane == 0) w[s] = part * SCALE + mask[b * SS + s];
    }
    __syncthreads();

    float l0 = w[tid], l1 = w[tid + 1024];
    red[tid] = fmaxf(l0, l1); __syncthreads();
    for (int off = 512; off; off >>= 1) {
        if (tid < off) red[tid] = fmaxf(red[tid], red[tid + off]);
        __syncthreads();
    }
    float mx = red[0];
    __syncthreads();

    float e0 = __expf(l0 - mx), e1 = __expf(l1 - mx);
    w[tid] = e0; w[tid + 1024] = e1;
    red[tid] = e0 + e1; __syncthreads();
    for (int off = 512; off; off >>= 1) {
        if (tid < off) red[tid] += red[tid + off];
        __syncthreads();
    }
    float inv = 1.0f / red[0];
    __syncthreads();

    int g = tid >> 6, dh = tid & 63;
    const float* kb2 = kb + dh;
    float acc = 0.0f;
    for (int s = g; s < SS; s += 16) acc += w[s] * kb2[(size_t)s * DD];
    red[tid] = acc; __syncthreads();
    if (tid < 64) {
        float t = 0.0f;
#pragma unroll
        for (int j = 0; j < 16; j++) t += red[tid + 64 * j];
        pk[blockIdx.x * DHH + tid] = t * inv;
    }
}

// ---------------------------------------------------------------------------
extern "C" void kernel_launch(void* const* d_in, const int* in_sizes, int n_in,
                              void* d_out, int out_size)
{
    const float* hs   = (const float*)d_in[0];
    const float* mask = (const float*)d_in[1];
    const float* Wq   = (const float*)d_in[2];
    const float* bq   = (const float*)d_in[3];
    const float* Wqa  = (const float*)d_in[4];
    const float* bqa  = (const float*)d_in[5];
    const float* Wk   = (const float*)d_in[6];
    const float* bk   = (const float*)d_in[7];
    const float* Wt   = (const float*)d_in[8];
    const float* bt   = (const float*)d_in[9];
    float* out = (float*)d_out;

    float *q, *k, *ql, *pq, *pk;
    __half *hsh, *a3h, *wq, *wk, *wt;
    cudaGetSymbolAddress((void**)&q,  g_q);
    cudaGetSymbolAddress((void**)&k,  g_k);
    cudaGetSymbolAddress((void**)&ql, g_ql);
    cudaGetSymbolAddress((void**)&pq, g_pq);
    cudaGetSymbolAddress((void**)&pk, g_pk);
    cudaGetSymbolAddress((void**)&hsh, g_hsh);
    cudaGetSymbolAddress((void**)&a3h, g_a3h);
    cudaGetSymbolAddress((void**)&wq, g_wq);
    cudaGetSymbolAddress((void**)&wk, g_wk);
    cudaGetSymbolAddress((void**)&wt, g_wt);

    cudaFuncSetAttribute(qlogits_kernel,
                         cudaFuncAttributeMaxDynamicSharedMemorySize, 65536);
    cudaFuncSetAttribute(gemm_tc,
                         cudaFuncAttributeMaxDynamicSharedMemorySize, SMEMB);

    const int conv_blocks = (MM * DD / 4) / 256;   // 16384
    dim3 wgrid(DD / 32, DD / 32);
    dim3 ggrid(DD / 128, MM / 128);                // (8, 128)

    // conversions
    conv_half<0><<<conv_blocks, 256>>>(hs, nullptr, hsh);
    conv_w<<<wgrid, 256>>>(Wq, wq);
    conv_w<<<wgrid, 256>>>(Wk, wk);
    conv_w<<<wgrid, 256>>>(Wt, wt);

    // q = hs @ Wq + bq ; k = hs @ Wk + bk  (HMMA fp16 single-pass)
    gemm_tc<<<ggrid, 256, SMEMB>>>(hsh, wq, bq, q, q, 0);
    gemm_tc<<<ggrid, 256, SMEMB>>>(hsh, wk, bk, k, k, 0);

    // q attention logits, softmax pools
    qlogits_kernel<<<MM / 32, 256, 65536>>>(Wqa, bqa, q, ql);
    softmax_pool_q<<<Bb * HH, 1024>>>(mask, ql, q, pq);
    softmax_pool_k<<<Bb * HH, 1024>>>(mask, k, pq, pk);

    // a3 = q * pk (broadcast over s), convert to fp16
    conv_half<1><<<conv_blocks, 256>>>(q, pk, a3h);

    // out = a3 @ Wt + bt + q
    gemm_tc<<<ggrid, 256, SMEMB>>>(a3h, wt, bt, q, out, 1);
}

// round 8
// speedup vs baseline: 7.8369x; 1.0745x over previous
#include <cuda_runtime.h>
#include <cuda_fp16.h>
#include <cstdint>
#include <math.h>

#define Bb 8
#define SS 2048
#define DD 1024
#define HH 16
#define DHH 64
#define MM (Bb * SS)
#define SCALE 0.125f
#define NCH 8               // S-chunks for pooling kernels
#define CHS (SS / NCH)      // 256

// ---------------- helpers ---------------------------------------------------
__device__ __forceinline__ uint32_t smem_to_u32(const void* p) {
    uint32_t a;
    asm("{ .reg .u64 t; cvta.to.shared.u64 t, %1; cvt.u32.u64 %0, t; }"
        : "=r"(a) : "l"(p));
    return a;
}
__device__ __forceinline__ void ldsm_x4(uint32_t* r, uint32_t addr) {
    asm volatile("ldmatrix.sync.aligned.m8n8.x4.shared.b16 {%0,%1,%2,%3}, [%4];"
        : "=r"(r[0]), "=r"(r[1]), "=r"(r[2]), "=r"(r[3]) : "r"(addr));
}
__device__ __forceinline__ void mma16816(float* c, const uint32_t* a,
                                         uint32_t b0, uint32_t b1) {
    asm volatile("mma.sync.aligned.m16n8k16.row.col.f32.f16.f16.f32 "
        "{%0,%1,%2,%3}, {%4,%5,%6,%7}, {%8,%9}, {%0,%1,%2,%3};"
        : "+f"(c[0]), "+f"(c[1]), "+f"(c[2]), "+f"(c[3])
        : "r"(a[0]), "r"(a[1]), "r"(a[2]), "r"(a[3]), "r"(b0), "r"(b1));
}
__device__ __forceinline__ void cp_async16(uint32_t saddr, const void* gaddr) {
    asm volatile("cp.async.cg.shared.global [%0], [%1], 16;"
        :: "r"(saddr), "l"(gaddr));
}
#define CP_COMMIT() asm volatile("cp.async.commit_group;" ::: "memory")
#define CP_WAIT_1() asm volatile("cp.async.wait_group 1;" ::: "memory")
#define CP_WAIT_0() asm volatile("cp.async.wait_group 0;" ::: "memory")

// ---------------- scratch (device globals) ---------------------------------
__device__ float g_q[(size_t)MM * DD];
__device__ float g_k[(size_t)MM * DD];
__device__ float g_qlt[Bb * HH * SS];       // q logits, [bh][s]
__device__ float g_qkl[Bb * HH * SS];       // qk logits, [bh][s]
__device__ float g_statq[Bb * HH * 2];
__device__ float g_statk[Bb * HH * 2];
__device__ float g_part[Bb * HH * NCH * DHH];
__device__ float g_pq[Bb * HH * DHH];
__device__ float g_pk[Bb * HH * DHH];
__device__ __half g_hsh[(size_t)MM * DD];
__device__ __half g_a3h[(size_t)MM * DD];
__device__ __half g_wq[DD * DD];
__device__ __half g_wk[DD * DD];
__device__ __half g_wt[DD * DD];

// ---------------- conversion: fp32 -> fp16 (optional pk multiply) ----------
template <int MUL>
__global__ void __launch_bounds__(256)
conv_half(const float* __restrict__ X, const float* __restrict__ pk,
          __half* __restrict__ out)
{
    size_t e = (size_t)blockIdx.x * 256 + threadIdx.x;  // float4 index
    float4 v = ((const float4*)X)[e];
    if (MUL) {
        size_t row = e >> 8;               // e / (DD/4)
        int batch = (int)(row >> 11);      // row / SS
        int col4 = (int)(e & 255);
        float4 p = ((const float4*)(pk + (size_t)batch * DD))[col4];
        v.x *= p.x; v.y *= p.y; v.z *= p.z; v.w *= p.w;
    }
    __half hv[4];
    hv[0] = __float2half_rn(v.x); hv[1] = __float2half_rn(v.y);
    hv[2] = __float2half_rn(v.z); hv[3] = __float2half_rn(v.w);
    ((uint2*)out)[e] = *(uint2*)hv;
}

// ---------------- conversion: weight transpose to fp16 ---------------------
__global__ void __launch_bounds__(256)
conv_w(const float* __restrict__ W, __half* __restrict__ wt)
{
    __shared__ float s[32][33];
    int n0 = blockIdx.x * 32, k0 = blockIdx.y * 32;
    int tx = threadIdx.x & 31, ty = threadIdx.x >> 5;  // 32 x 8
#pragma unroll
    for (int i = 0; i < 4; i++) {
        int r = ty + i * 8;
        s[r][tx] = W[(size_t)(k0 + r) * DD + n0 + tx];
    }
    __syncthreads();
#pragma unroll
    for (int i = 0; i < 4; i++) {
        int r = ty + i * 8;
        wt[(size_t)(n0 + r) * DD + k0 + tx] = __float2half_rn(s[tx][r]);
    }
}

// ---------------- HMMA GEMM: C[M,N] = A @ B^T + bias -----------------------
constexpr int PITCH = 80;                  // bytes per 32-elem fp16 row
constexpr int TILEB = 128 * PITCH;         // 10240
constexpr int STAGEB = 2 * TILEB;          // 20480
constexpr int SMEMB = 3 * STAGEB;          // 61440
constexpr int NKT = 32;

__global__ void __launch_bounds__(256, 2)
gemm_tc(const __half* __restrict__ Ah, const __half* __restrict__ Bw,
        const float* __restrict__ bias, const float* __restrict__ resid,
        float* __restrict__ C, int addResid)
{
    extern __shared__ char smem[];
    const uint32_t sb = smem_to_u32(smem);
    const int tid = threadIdx.x, wid = tid >> 5, lane = tid & 31;
    const int warp_m = wid & 3, warp_n = wid >> 2;
    const int n0 = blockIdx.x * 128;
    const int m0 = blockIdx.y * 128;

    float acc[2][8][4];
#pragma unroll
    for (int i = 0; i < 2; i++)
#pragma unroll
        for (int j = 0; j < 8; j++)
#pragma unroll
            for (int l = 0; l < 4; l++) acc[i][j][l] = 0.0f;

    auto load_stage = [&](int kt, int st) {
        const int k0 = kt * 32;
#pragma unroll
        for (int tile = 0; tile < 2; tile++) {
            const int rowoff = (tile == 0) ? m0 : n0;
            const __half* base = (tile == 0) ? Ah : Bw;
#pragma unroll
            for (int h = 0; h < 2; h++) {
                int c = tid + h * 256;           // 0..511
                int row = c >> 2, cc = c & 3;
                uint32_t sa = sb + st * STAGEB + tile * TILEB + row * PITCH + cc * 16;
                cp_async16(sa, base + (size_t)(rowoff + row) * DD + k0 + cc * 8);
            }
        }
    };

    load_stage(0, 0); CP_COMMIT();
    load_stage(1, 1); CP_COMMIT();

    for (int kt = 0; kt < NKT; kt++) {
        if (kt == NKT - 1) { CP_WAIT_0(); } else { CP_WAIT_1(); }
        __syncthreads();
        if (kt + 2 < NKT) {
            load_stage(kt + 2, (kt + 2) % 3);
            CP_COMMIT();
        }

        const uint32_t s0 = sb + (kt % 3) * STAGEB;
        const int rsel = lane & 15;
        const int hsel = (lane >> 4) * 16;

#pragma unroll
        for (int kp = 0; kp < 2; kp++) {
            uint32_t ah[2][4];
            const int ksel = hsel + kp * 32;
#pragma unroll
            for (int mi = 0; mi < 2; mi++) {
                uint32_t off = (uint32_t)(warp_m * 32 + mi * 16 + rsel) * PITCH + ksel;
                ldsm_x4(ah[mi], s0 + off);
            }
#pragma unroll
            for (int np = 0; np < 4; np++) {
                uint32_t off = (uint32_t)(warp_n * 64 + np * 16 + rsel) * PITCH + ksel;
                uint32_t bh[4];
                ldsm_x4(bh, s0 + TILEB + off);
#pragma unroll
                for (int mi = 0; mi < 2; mi++) {
                    mma16816(acc[mi][2 * np],     ah[mi], bh[0], bh[2]);
                    mma16816(acc[mi][2 * np + 1], ah[mi], bh[1], bh[3]);
                }
            }
        }
    }

    // ---------------- epilogue ----------------
#pragma unroll
    for (int mi = 0; mi < 2; mi++) {
        int row = m0 + warp_m * 32 + mi * 16 + (lane >> 2);
#pragma unroll
        for (int ni = 0; ni < 8; ni++) {
            int col = n0 + warp_n * 64 + ni * 8 + (lane & 3) * 2;
            float b0 = __ldg(bias + col), b1 = __ldg(bias + col + 1);
            float2 v0, v1;
            v0.x = acc[mi][ni][0] + b0;  v0.y = acc[mi][ni][1] + b1;
            v1.x = acc[mi][ni][2] + b0;  v1.y = acc[mi][ni][3] + b1;
            if (addResid) {
                float2 r0 = *(const float2*)(resid + (size_t)row * DD + col);
                float2 r1 = *(const float2*)(resid + (size_t)(row + 8) * DD + col);
                v0.x += r0.x; v0.y += r0.y; v1.x += r1.x; v1.y += r1.y;
            }
            *(float2*)(C + (size_t)row * DD + col) = v0;
            *(float2*)(C + (size_t)(row + 8) * DD + col) = v1;
        }
    }
}

// ---------------- q attention logits (transposed output [bh][s]) -----------
__global__ void __launch_bounds__(256)
qlogits_kernel(const float* __restrict__ Wqa, const float* __restrict__ bqa,
               const float* __restrict__ q, float* __restrict__ qlt)
{
    extern __shared__ float sW[];   // [HH][DD] transposed, 64 KB
    int tid = threadIdx.x;
    for (int i = tid; i < DD * HH; i += 256) {
        int k = i >> 4, h = i & 15;
        sW[h * DD + k] = Wqa[i];
    }
    __syncthreads();

    int warp = tid >> 5, lane = tid & 31;
    for (int rr = 0; rr < 4; rr++) {
        int m = blockIdx.x * 32 + warp * 4 + rr;
        const float* qrow = q + (size_t)m * DD;
        float acc[HH];
#pragma unroll
        for (int h = 0; h < HH; h++) acc[h] = 0.0f;
        for (int k = lane; k < DD; k += 32) {
            float qv = qrow[k];
#pragma unroll
            for (int h = 0; h < HH; h++) acc[h] += qv * sW[h * DD + k];
        }
#pragma unroll
        for (int h = 0; h < HH; h++)
#pragma unroll
            for (int off = 16; off; off >>= 1)
                acc[h] += __shfl_xor_sync(0xffffffffu, acc[h], off);
        if (lane == 0) {
            int b = m >> 11, s = m & (SS - 1);
#pragma unroll
            for (int h = 0; h < HH; h++)
                qlt[((size_t)(b * HH + h)) * SS + s] = acc[h] + bqa[h];
        }
    }
}

// ---------------- softmax stats: per (b,h) max + 1/sum ---------------------
__global__ void __launch_bounds__(256)
stats_kernel(const float* __restrict__ lt, const float* __restrict__ mask,
             float* __restrict__ stat)
{
    __shared__ float red[256];
    int bh = blockIdx.x, b = bh >> 4;
    int tid = threadIdx.x;
    const float* lrow = lt + (size_t)bh * SS;
    const float* mrow = mask + (size_t)b * SS;

    float lv[8];
    float lmax = -1e30f;
#pragma unroll
    for (int i = 0; i < 8; i++) {
        int s = tid + i * 256;
        lv[i] = lrow[s] * SCALE + mrow[s];
        lmax = fmaxf(lmax, lv[i]);
    }
    red[tid] = lmax; __syncthreads();
    for (int off = 128; off; off >>= 1) {
        if (tid < off) red[tid] = fmaxf(red[tid], red[tid + off]);
        __syncthreads();
    }
    float mx = red[0];
    __syncthreads();

    float lsum = 0.0f;
#pragma unroll
    for (int i = 0; i < 8; i++) lsum += __expf(lv[i] - mx);
    red[tid] = lsum; __syncthreads();
    for (int off = 128; off; off >>= 1) {
        if (tid < off) red[tid] += red[tid + off];
        __syncthreads();
    }
    if (tid == 0) { stat[bh * 2] = mx; stat[bh * 2 + 1] = 1.0f / red[0]; }
}

// ---------------- weighted pool partial over an S-chunk --------------------
// grid (NCH, B*H), 256 threads. partial[(bh*NCH+ch)*64+dh]
__global__ void __launch_bounds__(256)
poolpart_kernel(const float* __restrict__ lt, const float* __restrict__ mask,
                const float* __restrict__ stat, const float* __restrict__ src,
                float* __restrict__ part)
{
    __shared__ float w[CHS];
    __shared__ float red[256];
    int ch = blockIdx.x, bh = blockIdx.y;
    int b = bh >> 4, h = bh & 15;
    int s0 = ch * CHS;
    int t = threadIdx.x;

    float mx = stat[bh * 2], inv = stat[bh * 2 + 1];
    float l = lt[(size_t)bh * SS + s0 + t] * SCALE + mask[(size_t)b * SS + s0 + t];
    w[t] = __expf(l - mx) * inv;
    __syncthreads();

    int dh = t & 63, sg = t >> 6;          // 4 s-groups x 64 dh
    const float* src2 = src + ((size_t)(b * SS + s0 + sg)) * DD + h * DHH + dh;
    float acc = 0.0f;
#pragma unroll 16
    for (int i = 0; i < CHS / 4; i++)
        acc += w[sg + 4 * i] * src2[(size_t)4 * i * DD];
    red[t] = acc; __syncthreads();
    if (t < 64)
        part[((size_t)bh * NCH + ch) * DHH + t] =
            red[t] + red[t + 64] + red[t + 128] + red[t + 192];
}

// ---------------- reduce partials -> pooled [bh][64] ------------------------
__global__ void __launch_bounds__(64)
poolred_kernel(const float* __restrict__ part, float* __restrict__ out)
{
    int bh = blockIdx.x, t = threadIdx.x;
    float acc = 0.0f;
#pragma unroll
    for (int c = 0; c < NCH; c++)
        acc += part[((size_t)bh * NCH + c) * DHH + t];
    out[(size_t)bh * DHH + t] = acc;
}

// ---------------- qk logits: qkl[bh][s] = k[b,s,h*64:] . pq[bh] ------------
// grid (NCH, B*H), 256 threads (8 warps x 32 s each)
__global__ void __launch_bounds__(256)
qk_logits_kernel(const float* __restrict__ kx, const float* __restrict__ pq,
                 float* __restrict__ qkl)
{
    __shared__ float spq[DHH];
    int ch = blockIdx.x, bh = blockIdx.y;
    int b = bh >> 4, h = bh & 15;
    int t = threadIdx.x;
    if (t < DHH) spq[t] = pq[(size_t)bh * DHH + t];
    __syncthreads();

    int warp = t >> 5, lane = t & 31;
    float p0 = spq[lane], p1 = spq[lane + 32];
    const float* kb = kx + ((size_t)b * SS) * DD + h * DHH;
    int sbase = ch * CHS + warp * 32;
#pragma unroll 4
    for (int i = 0; i < 32; i++) {
        int s = sbase + i;
        const float* kr = kb + (size_t)s * DD;
        float part = kr[lane] * p0 + kr[lane + 32] * p1;
#pragma unroll
        for (int off = 16; off; off >>= 1)
            part += __shfl_xor_sync(0xffffffffu, part, off);
        if (lane == 0) qkl[(size_t)bh * SS + s] = part;
    }
}

// ---------------------------------------------------------------------------
extern "C" void kernel_launch(void* const* d_in, const int* in_sizes, int n_in,
                              void* d_out, int out_size)
{
    const float* hs   = (const float*)d_in[0];
    const float* mask = (const float*)d_in[1];
    const float* Wq   = (const float*)d_in[2];
    const float* bq   = (const float*)d_in[3];
    const float* Wqa  = (const float*)d_in[4];
    const float* bqa  = (const float*)d_in[5];
    const float* Wk   = (const float*)d_in[6];
    const float* bk   = (const float*)d_in[7];
    const float* Wt   = (const float*)d_in[8];
    const float* bt   = (const float*)d_in[9];
    float* out = (float*)d_out;

    float *q, *k, *qlt, *qkl, *statq, *statk, *partp, *pq, *pk;
    __half *hsh, *a3h, *wq, *wk, *wt;
    cudaGetSymbolAddress((void**)&q,  g_q);
    cudaGetSymbolAddress((void**)&k,  g_k);
    cudaGetSymbolAddress((void**)&qlt, g_qlt);
    cudaGetSymbolAddress((void**)&qkl, g_qkl);
    cudaGetSymbolAddress((void**)&statq, g_statq);
    cudaGetSymbolAddress((void**)&statk, g_statk);
    cudaGetSymbolAddress((void**)&partp, g_part);
    cudaGetSymbolAddress((void**)&pq, g_pq);
    cudaGetSymbolAddress((void**)&pk, g_pk);
    cudaGetSymbolAddress((void**)&hsh, g_hsh);
    cudaGetSymbolAddress((void**)&a3h, g_a3h);
    cudaGetSymbolAddress((void**)&wq, g_wq);
    cudaGetSymbolAddress((void**)&wk, g_wk);
    cudaGetSymbolAddress((void**)&wt, g_wt);

    cudaFuncSetAttribute(qlogits_kernel,
                         cudaFuncAttributeMaxDynamicSharedMemorySize, 65536);
    cudaFuncSetAttribute(gemm_tc,
                         cudaFuncAttributeMaxDynamicSharedMemorySize, SMEMB);

    const int conv_blocks = (MM * DD / 4) / 256;   // 16384
    dim3 wgrid(DD / 32, DD / 32);
    dim3 ggrid(DD / 128, MM / 128);                // (8, 128)
    dim3 pgrid(NCH, Bb * HH);                      // (8, 128)

    // conversions
    conv_half<0><<<conv_blocks, 256>>>(hs, nullptr, hsh);
    conv_w<<<wgrid, 256>>>(Wq, wq);
    conv_w<<<wgrid, 256>>>(Wk, wk);
    conv_w<<<wgrid, 256>>>(Wt, wt);

    // q = hs @ Wq + bq ; k = hs @ Wk + bk
    gemm_tc<<<ggrid, 256, SMEMB>>>(hsh, wq, bq, q, q, 0);
    gemm_tc<<<ggrid, 256, SMEMB>>>(hsh, wk, bk, k, k, 0);

    // pooled_q path
    qlogits_kernel<<<MM / 32, 256, 65536>>>(Wqa, bqa, q, qlt);
    stats_kernel<<<Bb * HH, 256>>>(qlt, mask, statq);
    poolpart_kernel<<<pgrid, 256>>>(qlt, mask, statq, q, partp);
    poolred_kernel<<<Bb * HH, 64>>>(partp, pq);

    // pooled_k path
    qk_logits_kernel<<<pgrid, 256>>>(k, pq, qkl);
    stats_kernel<<<Bb * HH, 256>>>(qkl, mask, statk);
    poolpart_kernel<<<pgrid, 256>>>(qkl, mask, statk, k, partp);
    poolred_kernel<<<Bb * HH, 64>>>(partp, pk);

    // a3 = q * pk (broadcast over s), convert to fp16
    conv_half<1><<<conv_blocks, 256>>>(q, pk, a3h);

    // out = a3 @ Wt + bt + q
    gemm_tc<<<ggrid, 256, SMEMB>>>(a3h, wt, bt, q, out, 1);
}